// round 14
// baseline (speedup 1.0000x reference)
#include <cuda_runtime.h>
#include <cuda_fp16.h>
#include <cstdint>

#define N_Q    4096
#define N_R    65536
#define DIM    512
#define K_TOP  16

#define BM     128
#define BN     256
#define BK     32
#define NSPLIT 64
#define CHUNK  (N_R / NSPLIT)   // 1024
#define NT     (CHUNK / BN)     // 4
#define NKT    (DIM / BK)       // 16
#define TOT    (NT * NKT)       // 64
#define NMB    (N_Q / BM)       // 32

#define PITCH   80                  // bytes per smem row (64 data + 16 pad)
#define A_STG   (BM * PITCH)        // 10240
#define B_STG   (BN * PITCH)        // 20480
#define A_OFF   0
#define B_OFF   (2 * A_STG)         // 20480
#define SP_OFF  (B_OFF + 2 * B_STG) // 61440
#define SPITCH_U 68                 // uint32 per spill row (64 half2 + 4 pad)
#define TS_OFF  (SP_OFF + BM * SPITCH_U * 4)   // 96256
#define SMEM_TOTAL (TS_OFF + 256 * 17 * 4)     // 113664

#define REF_BLOCKS ((N_R * DIM) / (256 * 8))   // 16384
#define X_BLOCKS   (N_Q / 2)                   // 2048

// ---------------- scratch ----------------
__device__ __half g_xh[(size_t)N_Q * DIM];               // 4 MB
__device__ __half g_rh[(size_t)N_R * DIM];               // 64 MB
__device__ __half g_cand[(size_t)N_Q * NSPLIT * K_TOP];  // 8 MB
__device__ int    g_ticket[NMB];

// ---------------- helpers ----------------
__device__ __forceinline__ uint32_t smem_u32(const void* p) {
    uint32_t a;
    asm("{ .reg .u64 t; cvta.to.shared.u64 t, %1; cvt.u32.u64 %0, t; }" : "=r"(a) : "l"(p));
    return a;
}
__device__ __forceinline__ void cp_async16(uint32_t dst, const void* src) {
    asm volatile("cp.async.cg.shared.global [%0], [%1], 16;\n" :: "r"(dst), "l"(src));
}
__device__ __forceinline__ void cp_commit() { asm volatile("cp.async.commit_group;\n" ::: "memory"); }
__device__ __forceinline__ void cp_wait_all() { asm volatile("cp.async.wait_group 0;\n" ::: "memory"); }

__device__ __forceinline__ void mma_f16acc(uint32_t* c, const uint32_t* a, const uint32_t* b) {
    asm volatile(
        "mma.sync.aligned.m16n8k16.row.col.f16.f16.f16.f16 "
        "{%0,%1}, {%2,%3,%4,%5}, {%6,%7}, {%0,%1};\n"
        : "+r"(c[0]), "+r"(c[1])
        : "r"(a[0]), "r"(a[1]), "r"(a[2]), "r"(a[3]),
          "r"(b[0]), "r"(b[1]));
}
#define LDSM4(r0, r1, r2, r3, addr) \
    asm volatile("ldmatrix.sync.aligned.m8n8.x4.shared.b16 {%0,%1,%2,%3}, [%4];" \
                 : "=r"(r0), "=r"(r1), "=r"(r2), "=r"(r3) : "r"(addr))

// ---------------- unified prep: refs fp32->f16 + x normalize + ticket reset --
__global__ __launch_bounds__(256) void prep_kernel(const float* __restrict__ refs,
                                                   const float* __restrict__ x) {
    int b = blockIdx.x;
    if (b == 0 && threadIdx.x < NMB) g_ticket[threadIdx.x] = 0;
    if (b < REF_BLOCKS) {
        size_t i = ((size_t)b * 256 + threadIdx.x) * 8;
        const float4* r4 = (const float4*)(refs + i);
        float4 f0 = r4[0];
        float4 f1 = r4[1];
        __half h[8];
        h[0] = __float2half(f0.x); h[1] = __float2half(f0.y);
        h[2] = __float2half(f0.z); h[3] = __float2half(f0.w);
        h[4] = __float2half(f1.x); h[5] = __float2half(f1.y);
        h[6] = __float2half(f1.z); h[7] = __float2half(f1.w);
        *(uint4*)(g_rh + i) = *(const uint4*)h;
    } else {
        int t = threadIdx.x & 127;
        int hh = threadIdx.x >> 7;
        int row = (b - REF_BLOCKS) * 2 + hh;
        const float* xr = x + (size_t)row * DIM;
        float v[4];
        float ss = 0.f;
#pragma unroll
        for (int i = 0; i < 4; ++i) { v[i] = xr[i * 128 + t]; ss += v[i] * v[i]; }
#pragma unroll
        for (int o = 16; o > 0; o >>= 1) ss += __shfl_xor_sync(0xffffffffu, ss, o);
        __shared__ float red[2][4];
        if ((t & 31) == 0) red[hh][t >> 5] = ss;
        __syncthreads();
        float tot = red[hh][0] + red[hh][1] + red[hh][2] + red[hh][3];
        float scale = 1.0f / fmaxf(sqrtf(tot), 1e-12f);
#pragma unroll
        for (int i = 0; i < 4; ++i)
            g_xh[(size_t)row * DIM + i * 128 + t] = __float2half(v[i] * scale);
    }
}

// ---------------- stage loader: A[128][32] + B[256][32] f16 ----------------
__device__ __forceinline__ void issue_stage(uint32_t sb, int buf, int j,
                                            const __half* Ag, const __half* Bg,
                                            int tid) {
    int nt = j >> 4;
    int kof = (j & 15) * BK;
    uint32_t abase = sb + A_OFF + buf * A_STG;
    uint32_t bbase = sb + B_OFF + buf * B_STG;
    const __half* Bt = Bg + (size_t)nt * BN * DIM;
#pragma unroll
    for (int h = 0; h < 2; ++h) {
        int ch = tid + h * 256;
        int row = ch >> 2, c = ch & 3;
        cp_async16(abase + row * PITCH + c * 16,
                   Ag + (size_t)row * DIM + kof + c * 8);
    }
#pragma unroll
    for (int h = 0; h < 4; ++h) {
        int ch = tid + h * 256;
        int row = ch >> 2, c = ch & 3;
        cp_async16(bbase + row * PITCH + c * 16,
                   Bt + (size_t)row * DIM + kof + c * 8);
    }
}

// ---------------- fused GEMM + top-16 + tail merge ----------------
__global__ __launch_bounds__(256, 2) void fused_gemm_topk_kernel(float* __restrict__ out) {
    extern __shared__ uint8_t smem[];
    uint32_t sb = smem_u32(smem);
    uint32_t* sp = (uint32_t*)(smem + SP_OFF);   // spill: [128][68] uint32 (half2)
    float*    ts = (float*)(smem + TS_OFF);      // [256][17] per-thread top-16
    __shared__ int is_last;

    int tid = threadIdx.x;
    int lane = tid & 31, warp = tid >> 5;
    int m0 = blockIdx.x * BM;
    int n0 = blockIdx.y * CHUNK;
    const __half* Ag = g_xh + (size_t)m0 * DIM;
    const __half* Bg = g_rh + (size_t)n0 * DIM;

    int wm = (warp >> 2) * 64;
    int wn = (warp & 3) * 64;
    int wph = (warp & 3) >> 1;
    int wnl = (wn & 127);
    int g = lane >> 2, q = lane & 3;

    uint32_t aoff = (uint32_t)((lane & 15) * PITCH + (lane >> 4) * 16);
    uint32_t boff = (uint32_t)((((lane >> 4) * 8) + (lane & 7)) * PITCH +
                               ((lane >> 3) & 1) * 16);

    int myrow = tid >> 1;
    int half_ = tid & 1;

#pragma unroll
    for (int j = 0; j < K_TOP; ++j) ts[tid * 17 + j] = -1e30f;

    uint32_t acc[32][2];
#pragma unroll
    for (int i = 0; i < 32; ++i) { acc[i][0] = 0u; acc[i][1] = 0u; }

    issue_stage(sb, 0, 0, Ag, Bg, tid);
    cp_commit();

    int it = 0;
    for (int nt = 0; nt < NT; ++nt) {
        for (int kt = 0; kt < NKT; ++kt) {
            cp_wait_all();
            __syncthreads();
            if (it + 1 < TOT) {
                issue_stage(sb, (it + 1) & 1, it + 1, Ag, Bg, tid);
                cp_commit();
            }
            int buf = it & 1;
            uint32_t abase = sb + A_OFF + buf * A_STG;
            uint32_t bbase = sb + B_OFF + buf * B_STG;
#pragma unroll
            for (int kk = 0; kk < 2; ++kk) {
                uint32_t af[4][4], bf[8][2];
#pragma unroll
                for (int mf = 0; mf < 4; ++mf) {
                    uint32_t ad = abase + (wm + mf * 16) * PITCH + kk * 32 + aoff;
                    LDSM4(af[mf][0], af[mf][1], af[mf][2], af[mf][3], ad);
                }
#pragma unroll
                for (int pr = 0; pr < 4; ++pr) {
                    uint32_t bd = bbase + (wn + pr * 16) * PITCH + kk * 32 + boff;
                    LDSM4(bf[pr * 2][0], bf[pr * 2][1],
                          bf[pr * 2 + 1][0], bf[pr * 2 + 1][1], bd);
                }
#pragma unroll
                for (int mf = 0; mf < 4; ++mf)
#pragma unroll
                    for (int nf = 0; nf < 8; ++nf)
                        mma_f16acc(acc[mf * 8 + nf], af[mf], bf[nf]);
            }
            ++it;
        }

        // epilogue: two 128-col phases
#pragma unroll
        for (int p = 0; p < 2; ++p) {
            __syncthreads();
            if (wph == p) {
#pragma unroll
                for (int mf = 0; mf < 4; ++mf) {
#pragma unroll
                    for (int nf = 0; nf < 8; ++nf) {
                        int r0 = wm + mf * 16 + g;
                        int cu = (wnl + nf * 8 + q * 2) >> 1;
                        sp[r0 * SPITCH_U + cu]       = acc[mf * 8 + nf][0];
                        sp[(r0 + 8) * SPITCH_U + cu] = acc[mf * 8 + nf][1];
                    }
                }
            }
            __syncthreads();
            {
                float t16[K_TOP];
#pragma unroll
                for (int j = 0; j < K_TOP; ++j) t16[j] = ts[tid * 17 + j];
                const uint32_t* rowp = sp + myrow * SPITCH_U + half_ * 32;
                float th = t16[K_TOP - 1];
#pragma unroll 8
                for (int j = 0; j < 32; ++j) {
                    __half2 h2 = *(const __half2*)&rowp[j];
                    float2 f2 = __half22float2(h2);
#pragma unroll
                    for (int e = 0; e < 2; ++e) {
                        float v = (e == 0) ? f2.x : f2.y;
                        if (v > th) {
                            t16[K_TOP - 1] = v;
#pragma unroll
                            for (int pp = K_TOP - 1; pp > 0; --pp) {
                                float a = t16[pp - 1], bb = t16[pp];
                                t16[pp - 1] = fmaxf(a, bb);
                                t16[pp]     = fminf(a, bb);
                            }
                            th = t16[K_TOP - 1];
                        }
                    }
                }
#pragma unroll
                for (int j = 0; j < K_TOP; ++j) ts[tid * 17 + j] = t16[j];
            }
        }
#pragma unroll
        for (int i = 0; i < 32; ++i) { acc[i][0] = 0u; acc[i][1] = 0u; }
    }

    // pair-merge col-halves, write candidates (f16, packed 2x uint4)
    __syncthreads();
    if (half_ == 0) {
        const float* a = &ts[tid * 17];
        const float* b = &ts[(tid + 1) * 17];
        __half m[K_TOP];
        int ia = 0, ib = 0;
#pragma unroll
        for (int j = 0; j < K_TOP; ++j) {
            float av = a[ia], bv = b[ib];
            float mv;
            if (av >= bv) { mv = av; ++ia; }
            else          { mv = bv; ++ib; }
            m[j] = __float2half(mv);
        }
        __half* outp = g_cand + ((size_t)(m0 + myrow) * NSPLIT + blockIdx.y) * K_TOP;
        ((uint4*)outp)[0] = ((const uint4*)m)[0];
        ((uint4*)outp)[1] = ((const uint4*)m)[1];
    }

    // ---- ticket: last split CTA of this m-block merges + writes weights ----
    __syncthreads();
    if (tid == 0) {
        __threadfence();
        int t = atomicAdd(&g_ticket[blockIdx.x], 1);
        is_last = (t == NSPLIT - 1) ? 1 : 0;
    }
    __syncthreads();
    if (!is_last) return;
    __threadfence();   // acquire: see all other CTAs' g_cand writes

    // thread pair (myrow, half_): scan 32 sorted lists each, keep top-16
    {
        const __half* base = g_cand + ((size_t)(m0 + myrow) * NSPLIT + half_ * 32) * K_TOP;
        float t16[K_TOP];
        // init from first list (already sorted descending)
        {
            uint4 u0 = ((const uint4*)base)[0];
            uint4 u1 = ((const uint4*)base)[1];
            const __half* h = (const __half*)&u0;
#pragma unroll
            for (int j = 0; j < 8; ++j) t16[j] = __half2float(h[j]);
            h = (const __half*)&u1;
#pragma unroll
            for (int j = 0; j < 8; ++j) t16[8 + j] = __half2float(h[j]);
        }
        float th = t16[K_TOP - 1];
        for (int s = 1; s < 32; ++s) {
            const uint4* lp = (const uint4*)(base + (size_t)s * K_TOP);
            uint4 u0 = lp[0];
            uint4 u1 = lp[1];
            __half hl[K_TOP];
            ((uint4*)hl)[0] = u0;
            ((uint4*)hl)[1] = u1;
#pragma unroll
            for (int j = 0; j < K_TOP; ++j) {
                float v = __half2float(hl[j]);
                if (v <= th) break;     // sorted descending: rest are smaller
                t16[K_TOP - 1] = v;
#pragma unroll
                for (int pp = K_TOP - 1; pp > 0; --pp) {
                    float a = t16[pp - 1], bb = t16[pp];
                    t16[pp - 1] = fmaxf(a, bb);
                    t16[pp]     = fminf(a, bb);
                }
                th = t16[K_TOP - 1];
            }
        }
#pragma unroll
        for (int j = 0; j < K_TOP; ++j) ts[tid * 17 + j] = t16[j];
    }
    __syncthreads();
    if (half_ == 0) {
        const float* a = &ts[tid * 17];
        const float* b = &ts[(tid + 1) * 17];
        float m[K_TOP];
        int ia = 0, ib = 0;
#pragma unroll
        for (int j = 0; j < K_TOP; ++j) {
            float av = a[ia], bv = b[ib];
            if (av >= bv) { m[j] = av; ++ia; }
            else          { m[j] = bv; ++ib; }
        }
        float w[K_TOP];
        float ssum = 0.f;
#pragma unroll
        for (int j = 0; j < K_TOP; ++j) {
            float d2 = fmaxf(2.0f - 2.0f * m[j], 1e-12f);
            w[j] = expf(-sqrtf(d2));
            ssum += w[j];
        }
        float inv = 1.0f / fmaxf(ssum, 1e-12f);
        float* op = out + (size_t)(m0 + myrow) * K_TOP;
#pragma unroll
        for (int j = 0; j < K_TOP; ++j) op[j] = w[j] * inv;
    }
}

// ---------------- launch ----------------
extern "C" void kernel_launch(void* const* d_in, const int* in_sizes, int n_in,
                              void* d_out, int out_size) {
    const float* x    = (const float*)d_in[0];
    const float* refs = (const float*)d_in[1];
    float* out = (float*)d_out;

    static bool attr_set = false;
    if (!attr_set) {
        cudaFuncSetAttribute(fused_gemm_topk_kernel,
                             cudaFuncAttributeMaxDynamicSharedMemorySize, SMEM_TOTAL);
        attr_set = true;
    }

    prep_kernel<<<REF_BLOCKS + X_BLOCKS, 256>>>(refs, x);
    fused_gemm_topk_kernel<<<dim3(N_Q / BM, NSPLIT), 256, SMEM_TOTAL>>>(out);
}

// round 15
// speedup vs baseline: 1.0333x; 1.0333x over previous
#include <cuda_runtime.h>
#include <cuda_fp16.h>
#include <cstdint>

#define N_Q    4096
#define N_R    65536
#define DIM    512
#define K_TOP  16

#define BM     128
#define BN     256
#define BK     32
#define NSPLIT 64
#define CHUNK  (N_R / NSPLIT)   // 1024
#define NT     (CHUNK / BN)     // 4
#define NKT    (DIM / BK)       // 16
#define TOT    (NT * NKT)       // 64

#define PITCH   80                  // bytes per smem row (64 data + 16 pad)
#define A_STG   (BM * PITCH)        // 10240
#define B_STG   (BN * PITCH)        // 20480
#define A_OFF   0
#define B_OFF   (2 * A_STG)         // 20480
#define SP_OFF  (B_OFF + 2 * B_STG) // 61440
#define SPITCH_U 68                 // uint32 per spill row (64 half2 + 4 pad)
#define TS_OFF  (SP_OFF + BM * SPITCH_U * 4)   // 96256
#define SMEM_TOTAL (TS_OFF + 256 * 17 * 4)     // 113664

#define REF_BLOCKS ((N_R * DIM) / (256 * 8))   // 16384
#define X_BLOCKS   (N_Q / 2)                   // 2048

// ---------------- scratch ----------------
__device__ __half g_xh[(size_t)N_Q * DIM];               // 4 MB
__device__ __half g_rh[(size_t)N_R * DIM];               // 64 MB
__device__ __half g_cand[(size_t)N_Q * NSPLIT * K_TOP];  // 8 MB

// ---------------- helpers ----------------
__device__ __forceinline__ uint32_t smem_u32(const void* p) {
    uint32_t a;
    asm("{ .reg .u64 t; cvta.to.shared.u64 t, %1; cvt.u32.u64 %0, t; }" : "=r"(a) : "l"(p));
    return a;
}
__device__ __forceinline__ void cp_async16(uint32_t dst, const void* src) {
    asm volatile("cp.async.cg.shared.global [%0], [%1], 16;\n" :: "r"(dst), "l"(src));
}
__device__ __forceinline__ void cp_commit() { asm volatile("cp.async.commit_group;\n" ::: "memory"); }
__device__ __forceinline__ void cp_wait_all() { asm volatile("cp.async.wait_group 0;\n" ::: "memory"); }

__device__ __forceinline__ void mma_f16acc(uint32_t* c, const uint32_t* a, const uint32_t* b) {
    asm volatile(
        "mma.sync.aligned.m16n8k16.row.col.f16.f16.f16.f16 "
        "{%0,%1}, {%2,%3,%4,%5}, {%6,%7}, {%0,%1};\n"
        : "+r"(c[0]), "+r"(c[1])
        : "r"(a[0]), "r"(a[1]), "r"(a[2]), "r"(a[3]),
          "r"(b[0]), "r"(b[1]));
}
#define LDSM4(r0, r1, r2, r3, addr) \
    asm volatile("ldmatrix.sync.aligned.m8n8.x4.shared.b16 {%0,%1,%2,%3}, [%4];" \
                 : "=r"(r0), "=r"(r1), "=r"(r2), "=r"(r3) : "r"(addr))

// ---------------- unified prep: refs fp32->f16 + x normalize->f16 ----------
__global__ __launch_bounds__(256) void prep_kernel(const float* __restrict__ refs,
                                                   const float* __restrict__ x) {
    int b = blockIdx.x;
    if (b < REF_BLOCKS) {
        size_t i = ((size_t)b * 256 + threadIdx.x) * 8;
        const float4* r4 = (const float4*)(refs + i);
        float4 f0 = r4[0];
        float4 f1 = r4[1];
        __half h[8];
        h[0] = __float2half(f0.x); h[1] = __float2half(f0.y);
        h[2] = __float2half(f0.z); h[3] = __float2half(f0.w);
        h[4] = __float2half(f1.x); h[5] = __float2half(f1.y);
        h[6] = __float2half(f1.z); h[7] = __float2half(f1.w);
        *(uint4*)(g_rh + i) = *(const uint4*)h;
    } else {
        int t = threadIdx.x & 127;
        int hh = threadIdx.x >> 7;
        int row = (b - REF_BLOCKS) * 2 + hh;
        const float* xr = x + (size_t)row * DIM;
        float v[4];
        float ss = 0.f;
#pragma unroll
        for (int i = 0; i < 4; ++i) { v[i] = xr[i * 128 + t]; ss += v[i] * v[i]; }
#pragma unroll
        for (int o = 16; o > 0; o >>= 1) ss += __shfl_xor_sync(0xffffffffu, ss, o);
        __shared__ float red[2][4];
        if ((t & 31) == 0) red[hh][t >> 5] = ss;
        __syncthreads();
        float tot = red[hh][0] + red[hh][1] + red[hh][2] + red[hh][3];
        float scale = 1.0f / fmaxf(sqrtf(tot), 1e-12f);
#pragma unroll
        for (int i = 0; i < 4; ++i)
            g_xh[(size_t)row * DIM + i * 128 + t] = __float2half(v[i] * scale);
    }
}

// ---------------- stage loader: A[128][32] + B[256][32] f16 ----------------
__device__ __forceinline__ void issue_stage(uint32_t sb, int buf, int j,
                                            const __half* Ag, const __half* Bg,
                                            int tid) {
    int nt = j >> 4;
    int kof = (j & 15) * BK;
    uint32_t abase = sb + A_OFF + buf * A_STG;
    uint32_t bbase = sb + B_OFF + buf * B_STG;
    const __half* Bt = Bg + (size_t)nt * BN * DIM;
#pragma unroll
    for (int h = 0; h < 2; ++h) {
        int ch = tid + h * 256;
        int row = ch >> 2, c = ch & 3;
        cp_async16(abase + row * PITCH + c * 16,
                   Ag + (size_t)row * DIM + kof + c * 8);
    }
#pragma unroll
    for (int h = 0; h < 4; ++h) {
        int ch = tid + h * 256;
        int row = ch >> 2, c = ch & 3;
        cp_async16(bbase + row * PITCH + c * 16,
                   Bt + (size_t)row * DIM + kof + c * 8);
    }
}

// ---------------- fused GEMM (64x64 warp tiles, f16 acc) + top-16 ----------------
__global__ __launch_bounds__(256, 2) void fused_gemm_topk_kernel() {
    extern __shared__ uint8_t smem[];
    uint32_t sb = smem_u32(smem);
    uint32_t* sp = (uint32_t*)(smem + SP_OFF);   // spill: [128][68] uint32 (half2)
    float*    ts = (float*)(smem + TS_OFF);      // [256][17] per-thread top-16

    int tid = threadIdx.x;
    int lane = tid & 31, warp = tid >> 5;
    int m0 = blockIdx.x * BM;
    int n0 = blockIdx.y * CHUNK;
    const __half* Ag = g_xh + (size_t)m0 * DIM;
    const __half* Bg = g_rh + (size_t)n0 * DIM;

    int wm = (warp >> 2) * 64;
    int wn = (warp & 3) * 64;
    int wph = (warp & 3) >> 1;
    int wnl = (wn & 127);
    int g = lane >> 2, q = lane & 3;

    uint32_t aoff = (uint32_t)((lane & 15) * PITCH + (lane >> 4) * 16);
    uint32_t boff = (uint32_t)((((lane >> 4) * 8) + (lane & 7)) * PITCH +
                               ((lane >> 3) & 1) * 16);

    int myrow = tid >> 1;
    int half_ = tid & 1;

#pragma unroll
    for (int j = 0; j < K_TOP; ++j) ts[tid * 17 + j] = -1e30f;

    uint32_t acc[32][2];
#pragma unroll
    for (int i = 0; i < 32; ++i) { acc[i][0] = 0u; acc[i][1] = 0u; }

    issue_stage(sb, 0, 0, Ag, Bg, tid);
    cp_commit();

    int it = 0;
    for (int nt = 0; nt < NT; ++nt) {
        for (int kt = 0; kt < NKT; ++kt) {
            cp_wait_all();
            __syncthreads();
            if (it + 1 < TOT) {
                issue_stage(sb, (it + 1) & 1, it + 1, Ag, Bg, tid);
                cp_commit();
            }
            int buf = it & 1;
            uint32_t abase = sb + A_OFF + buf * A_STG;
            uint32_t bbase = sb + B_OFF + buf * B_STG;
#pragma unroll
            for (int kk = 0; kk < 2; ++kk) {
                uint32_t af[4][4], bf[8][2];
#pragma unroll
                for (int mf = 0; mf < 4; ++mf) {
                    uint32_t ad = abase + (wm + mf * 16) * PITCH + kk * 32 + aoff;
                    LDSM4(af[mf][0], af[mf][1], af[mf][2], af[mf][3], ad);
                }
#pragma unroll
                for (int pr = 0; pr < 4; ++pr) {
                    uint32_t bd = bbase + (wn + pr * 16) * PITCH + kk * 32 + boff;
                    LDSM4(bf[pr * 2][0], bf[pr * 2][1],
                          bf[pr * 2 + 1][0], bf[pr * 2 + 1][1], bd);
                }
#pragma unroll
                for (int mf = 0; mf < 4; ++mf)
#pragma unroll
                    for (int nf = 0; nf < 8; ++nf)
                        mma_f16acc(acc[mf * 8 + nf], af[mf], bf[nf]);
            }
            ++it;
        }

        // epilogue: two 128-col phases
#pragma unroll
        for (int p = 0; p < 2; ++p) {
            __syncthreads();
            if (wph == p) {
#pragma unroll
                for (int mf = 0; mf < 4; ++mf) {
#pragma unroll
                    for (int nf = 0; nf < 8; ++nf) {
                        int r0 = wm + mf * 16 + g;
                        int cu = (wnl + nf * 8 + q * 2) >> 1;
                        sp[r0 * SPITCH_U + cu]       = acc[mf * 8 + nf][0];
                        sp[(r0 + 8) * SPITCH_U + cu] = acc[mf * 8 + nf][1];
                    }
                }
            }
            __syncthreads();
            {
                float t16[K_TOP];
#pragma unroll
                for (int j = 0; j < K_TOP; ++j) t16[j] = ts[tid * 17 + j];
                const uint32_t* rowp = sp + myrow * SPITCH_U + half_ * 32;
                float th = t16[K_TOP - 1];
#pragma unroll 8
                for (int j = 0; j < 32; ++j) {
                    __half2 h2 = *(const __half2*)&rowp[j];
                    float2 f2 = __half22float2(h2);
#pragma unroll
                    for (int e = 0; e < 2; ++e) {
                        float v = (e == 0) ? f2.x : f2.y;
                        if (v > th) {
                            t16[K_TOP - 1] = v;
#pragma unroll
                            for (int pp = K_TOP - 1; pp > 0; --pp) {
                                float a = t16[pp - 1], bb = t16[pp];
                                t16[pp - 1] = fmaxf(a, bb);
                                t16[pp]     = fminf(a, bb);
                            }
                            th = t16[K_TOP - 1];
                        }
                    }
                }
#pragma unroll
                for (int j = 0; j < K_TOP; ++j) ts[tid * 17 + j] = t16[j];
            }
        }
#pragma unroll
        for (int i = 0; i < 32; ++i) { acc[i][0] = 0u; acc[i][1] = 0u; }
    }

    // pair-merge col-halves, write candidates (f16, packed 2x uint4)
    __syncthreads();
    if (half_ == 0) {
        const float* a = &ts[tid * 17];
        const float* b = &ts[(tid + 1) * 17];
        __half m[K_TOP];
        int ia = 0, ib = 0;
#pragma unroll
        for (int j = 0; j < K_TOP; ++j) {
            float av = a[ia], bv = b[ib];
            float mv;
            if (av >= bv) { mv = av; ++ia; }
            else          { mv = bv; ++ib; }
            m[j] = __float2half(mv);
        }
        __half* outp = g_cand + ((size_t)(m0 + myrow) * NSPLIT + blockIdx.y) * K_TOP;
        ((uint4*)outp)[0] = ((const uint4*)m)[0];
        ((uint4*)outp)[1] = ((const uint4*)m)[1];
    }
}

// ---------------- final merge: 8 threads/query, sorted-list early break ----
__global__ __launch_bounds__(256) void merge_kernel(float* __restrict__ out) {
    int t = threadIdx.x;
    int qy = blockIdx.x * 32 + (t >> 3);
    int seg = t & 7;                 // this thread owns lists [seg*8, seg*8+8)
    const __half* base = g_cand + ((size_t)qy * NSPLIT + seg * 8) * K_TOP;

    // up-front: first half (8 values) of each of 8 lists -> MLP=8
    uint4 f[8];
#pragma unroll
    for (int l = 0; l < 8; ++l)
        f[l] = *(const uint4*)(base + (size_t)l * K_TOP);

    float t16[K_TOP];
    // init from list 0 (full 16)
    {
        const __half* h0 = (const __half*)&f[0];
#pragma unroll
        for (int j = 0; j < 8; ++j) t16[j] = __half2float(h0[j]);
        uint4 s0 = *(const uint4*)(base + 8);
        const __half* h1 = (const __half*)&s0;
#pragma unroll
        for (int j = 0; j < 8; ++j) t16[8 + j] = __half2float(h1[j]);
    }
    float th = t16[K_TOP - 1];

#pragma unroll
    for (int l = 1; l < 8; ++l) {
        const __half* h = (const __half*)&f[l];
        bool all8 = true;
#pragma unroll
        for (int j = 0; j < 8; ++j) {
            float v = __half2float(h[j]);
            if (v <= th) { all8 = false; break; }    // sorted desc: rest smaller
            t16[K_TOP - 1] = v;
#pragma unroll
            for (int pp = K_TOP - 1; pp > 0; --pp) {
                float a = t16[pp - 1], bb = t16[pp];
                t16[pp - 1] = fmaxf(a, bb);
                t16[pp]     = fminf(a, bb);
            }
            th = t16[K_TOP - 1];
        }
        if (all8) {   // rare: whole first half inserted -> need second half
            uint4 s = *(const uint4*)(base + (size_t)l * K_TOP + 8);
            const __half* h2 = (const __half*)&s;
#pragma unroll
            for (int j = 0; j < 8; ++j) {
                float v = __half2float(h2[j]);
                if (v <= th) break;
                t16[K_TOP - 1] = v;
#pragma unroll
                for (int pp = K_TOP - 1; pp > 0; --pp) {
                    float a = t16[pp - 1], bb = t16[pp];
                    t16[pp - 1] = fmaxf(a, bb);
                    t16[pp]     = fminf(a, bb);
                }
                th = t16[K_TOP - 1];
            }
        }
    }

    // warp-local tree merge (8 threads/query live in one warp)
    __shared__ float sm[256 * K_TOP];
#pragma unroll
    for (int j = 0; j < K_TOP; ++j) sm[t * K_TOP + j] = t16[j];

#pragma unroll
    for (int hl = 4; hl >= 1; hl >>= 1) {
        __syncwarp();
        if (seg < hl) {
            float* a = &sm[t * K_TOP];
            float* b = &sm[(t + hl) * K_TOP];
            float m[K_TOP];
            int ia = 0, ib = 0;
#pragma unroll
            for (int j = 0; j < K_TOP; ++j) {
                float av = a[ia], bv = b[ib];
                if (av >= bv) { m[j] = av; ++ia; }
                else          { m[j] = bv; ++ib; }
            }
#pragma unroll
            for (int j = 0; j < K_TOP; ++j) a[j] = m[j];
        }
    }
    __syncwarp();

    if (seg == 0) {
        const float* m = &sm[t * K_TOP];
        float w[K_TOP];
        float ssum = 0.f;
#pragma unroll
        for (int j = 0; j < K_TOP; ++j) {
            float d2 = fmaxf(2.0f - 2.0f * m[j], 1e-12f);
            w[j] = expf(-sqrtf(d2));
            ssum += w[j];
        }
        float inv = 1.0f / fmaxf(ssum, 1e-12f);
        float* op = out + (size_t)qy * K_TOP;
#pragma unroll
        for (int j = 0; j < K_TOP; ++j) op[j] = w[j] * inv;
    }
}

// ---------------- launch ----------------
extern "C" void kernel_launch(void* const* d_in, const int* in_sizes, int n_in,
                              void* d_out, int out_size) {
    const float* x    = (const float*)d_in[0];
    const float* refs = (const float*)d_in[1];
    float* out = (float*)d_out;

    static bool attr_set = false;
    if (!attr_set) {
        cudaFuncSetAttribute(fused_gemm_topk_kernel,
                             cudaFuncAttributeMaxDynamicSharedMemorySize, SMEM_TOTAL);
        attr_set = true;
    }

    prep_kernel<<<REF_BLOCKS + X_BLOCKS, 256>>>(refs, x);
    fused_gemm_topk_kernel<<<dim3(N_Q / BM, NSPLIT), 256, SMEM_TOTAL>>>();
    merge_kernel<<<N_Q / 32, 256>>>(out);
}